// round 6
// baseline (speedup 1.0000x reference)
#include <cuda_runtime.h>
#include <cuda_bf16.h>
#include <cstdint>

// fast softplus: max(x,0) + log(1 + exp(-|x|)); abs error ~1e-7, tolerance is 1e-3
__device__ __forceinline__ float softplus_f(float x) {
    return fmaxf(x, 0.0f) + __logf(1.0f + __expf(-fabsf(x)));
}

__device__ __forceinline__ uint32_t smem_u32(const void* p) {
    return (uint32_t)__cvta_generic_to_shared(p);
}

#define MBAR_INIT(addr, cnt) \
    asm volatile("mbarrier.init.shared.b64 [%0], %1;" :: "r"(addr), "r"(cnt) : "memory")
#define MBAR_EXPECT_TX(addr, bytes) \
    asm volatile("mbarrier.arrive.expect_tx.shared.b64 _, [%0], %1;" :: "r"(addr), "r"(bytes) : "memory")
#define BULK_G2S(dst_smem, src_gmem, nbytes, bar) \
    asm volatile("cp.async.bulk.shared::cta.global.mbarrier::complete_tx::bytes [%0], [%1], %2, [%3];" \
                 :: "r"(dst_smem), "l"(src_gmem), "r"(nbytes), "r"(bar) : "memory")

__device__ __forceinline__ void mbar_wait_parity(uint32_t bar, uint32_t parity) {
    uint32_t done;
    asm volatile(
        "{\n\t.reg .pred p;\n\t"
        "mbarrier.try_wait.parity.acquire.cta.shared::cta.b64 p, [%1], %2;\n\t"
        "selp.b32 %0, 1, 0, p;\n\t}"
        : "=r"(done) : "r"(bar), "r"(parity) : "memory");
    while (!done) {
        asm volatile(
            "{\n\t.reg .pred p;\n\t"
            "mbarrier.try_wait.parity.acquire.cta.shared::cta.b64 p, [%1], %2, 0x989680;\n\t"
            "selp.b32 %0, 1, 0, p;\n\t}"
            : "=r"(done) : "r"(bar), "r"(parity) : "memory");
    }
}

// One CTA per batch row. Whole row (T*16B <= 128KB) staged into SMEM via
// cp.async.bulk, all chunks issued up front. 4 elems/thread per chunk:
// own-f only (boundary via shfl_up, lane0 recomputes from SMEM), one
// two-level block scan per chunk, STG.128 stores.
template <int NTHREADS, int CELEMS, int MAXCHUNK>
__global__ __launch_bounds__(NTHREADS, 1)
void soc_kernel(const float4* __restrict__ X,       // (B, T, 4)
                const float*  __restrict__ SC,      // (B, 4)
                const float*  __restrict__ W1i, const float* __restrict__ b1i,
                const float*  __restrict__ W2i, const float* __restrict__ b2i,
                const float*  __restrict__ W1e, const float* __restrict__ b1e,
                const float*  __restrict__ W2e, const float* __restrict__ b2e,
                float* __restrict__ out,            // (B, T)
                int T)
{
    extern __shared__ __align__(128) float4 xbuf[];    // MAXCHUNK * CELEMS float4
    __shared__ __align__(8) uint64_t mbar[MAXCHUNK];
    __shared__ float warp_tot[2][NTHREADS / 32];       // double-buffered
    __shared__ float bnd_ts, bnd_f;                    // chunk-boundary carry

    const int b    = blockIdx.x;
    const int tid  = threadIdx.x;
    const int lane = tid & 31;
    const int warp = tid >> 5;
    constexpr int NW = NTHREADS / 32;
    const unsigned FULL = 0xFFFFFFFFu;
    const long long rowbase = (long long)b * (long long)T;
    const int nchunks = (T + CELEMS - 1) / CELEMS;     // <= MAXCHUNK

    // ---- init barriers, then issue ALL bulk copies up front ----
    if (tid == 0) {
        #pragma unroll
        for (int c = 0; c < MAXCHUNK; c++)
            MBAR_INIT(smem_u32(&mbar[c]), 1);
    }
    __syncthreads();
    if (tid == 0) {
        for (int c = 0; c < nchunks; c++) {
            const int lim = min(CELEMS, T - c * CELEMS);
            const uint32_t nbytes = (uint32_t)lim * 16u;
            const uint32_t bar = smem_u32(&mbar[c]);
            MBAR_EXPECT_TX(bar, nbytes);
            BULK_G2S(smem_u32(&xbuf[c * CELEMS]),
                     (const void*)(X + rowbase + (long long)c * CELEMS),
                     nbytes, bar);
        }
    }

    // Per-batch scalars (overlaps with TMA flight)
    const float Q    = SC[b * 4 + 0];
    const float eta0 = SC[b * 4 + 1];
    const float R    = SC[b * 4 + 2];
    const float S3   = SC[b * 4 + 3];
    const float w1e0 = W1e[0], w1e1 = W1e[1];
    const float be1  = b1e[0];
    const float w2e  = W2e[0];
    const float be2  = b2e[0];
    const float w1i0 = W1i[0], w1i1 = W1i[1], w1i2 = W1i[2], w1i3 = W1i[3];
    const float bi1  = b1i[0], w2i = W2i[0], bi2 = b2i[0];
    const float scale = eta0 / (3600.0f * Q);

    float base = 0.0f;   // SOC_init + running cumsum carry (set at c==0)

    for (int c = 0; c < nchunks; c++) {
        mbar_wait_parity(smem_u32(&mbar[c]), 0);

        const float4* xb = &xbuf[c * CELEMS];
        const int lim = min(CELEMS, T - c * CELEMS);
        const int s = tid * 4;                 // element index within chunk

        if (c == 0) {
            float4 x0 = xb[0];
            float h0 = softplus_f(x0.y * w1i0 + x0.z * w1i1 + x0.w * w1i2 + R * w1i3 + bi1);
            base = S3 * (1.0f + (h0 * w2i + bi2));
        }

        float i0 = 0.f, i1 = 0.f, i2 = 0.f, i3 = 0.f;
        float ts3 = 0.f, f3 = 0.f;             // last-elem (ts,f) for shfl / bnd

        if (s + 3 < lim) {
            // fast path: full 4-element group
            float4 v0 = xb[s + 0];
            float4 v1 = xb[s + 1];
            float4 v2 = xb[s + 2];
            float4 v3 = xb[s + 3];
            float h0e = softplus_f(fmaf(v0.y, w1e0, fmaf(v0.z, w1e1, be1)));
            float h1e = softplus_f(fmaf(v1.y, w1e0, fmaf(v1.z, w1e1, be1)));
            float h2e = softplus_f(fmaf(v2.y, w1e0, fmaf(v2.z, w1e1, be1)));
            float h3e = softplus_f(fmaf(v3.y, w1e0, fmaf(v3.z, w1e1, be1)));
            float f0 = scale * (1.0f + fmaf(h0e, w2e, be2)) * v0.y;
            float f1 = scale * (1.0f + fmaf(h1e, w2e, be2)) * v1.y;
            float f2 = scale * (1.0f + fmaf(h2e, w2e, be2)) * v2.y;
            f3       = scale * (1.0f + fmaf(h3e, w2e, be2)) * v3.y;
            ts3 = v3.x;

            // previous lane's last (ts, f)
            float pts = __shfl_up_sync(FULL, ts3, 1);
            float pf  = __shfl_up_sync(FULL, f3, 1);
            if (lane == 0) {
                if (s > 0) {                   // cross-warp boundary: recompute
                    float4 vp = xb[s - 1];
                    float hp = softplus_f(fmaf(vp.y, w1e0, fmaf(vp.z, w1e1, be1)));
                    pts = vp.x;
                    pf  = scale * (1.0f + fmaf(hp, w2e, be2)) * vp.y;
                } else if (c > 0) {            // chunk boundary carry
                    pts = bnd_ts; pf = bnd_f;
                }
            }
            if (c > 0 || s > 0 || lane > 0)    // global t==0 has no increment
                i0 = (v0.x - pts) * pf;
            else
                i0 = 0.0f;
            if (s == 0 && c == 0 && lane == 0) i0 = 0.0f;
            i1 = (v1.x - v0.x) * f0;
            i2 = (v2.x - v1.x) * f1;
            i3 = (v3.x - v2.x) * f2;
        } else {
            // tail path (scalar, rare)
            float pts = 0.f, pf = 0.f;
            bool havep = false;
            if (s < lim && (s > 0 || c > 0)) {
                if (s > 0) {
                    float4 vp = xb[s - 1];
                    float hp = softplus_f(fmaf(vp.y, w1e0, fmaf(vp.z, w1e1, be1)));
                    pts = vp.x;
                    pf  = scale * (1.0f + fmaf(hp, w2e, be2)) * vp.y;
                } else { pts = bnd_ts; pf = bnd_f; }
                havep = true;
            }
            float acc[4] = {0.f, 0.f, 0.f, 0.f};
            for (int j = 0; j < 4; j++) {
                const int t = s + j;
                if (t < lim) {
                    float4 v = xb[t];
                    if (havep) acc[j] = (v.x - pts) * pf;
                    float h = softplus_f(fmaf(v.y, w1e0, fmaf(v.z, w1e1, be1)));
                    pts = v.x;
                    pf  = scale * (1.0f + fmaf(h, w2e, be2)) * v.y;
                    havep = true;
                    ts3 = pts; f3 = pf;
                }
            }
            i0 = acc[0]; i1 = acc[1]; i2 = acc[2]; i3 = acc[3];
        }

        const float p0 = i0;
        const float p1 = p0 + i1;
        const float p2 = p1 + i2;
        const float run = p2 + i3;

        // ---- two-level block scan of per-thread totals ----
        float v = run;
        #pragma unroll
        for (int d = 1; d < 32; d <<= 1) {
            float o = __shfl_up_sync(FULL, v, d);
            if (lane >= d) v += o;
        }
        const int cb = c & 1;
        if (lane == 31) warp_tot[cb][warp] = v;
        __syncthreads();                       // sync1

        // boundary carry for the NEXT chunk (ordered by sync2 below)
        if (s == ((lim - 1) & ~3)) { bnd_ts = ts3; bnd_f = f3; }

        if (warp == 0 && lane < NW) {
            float w = warp_tot[cb][lane];
            #pragma unroll
            for (int d = 1; d < NW; d <<= 1) {
                float o = __shfl_up_sync(FULL, w, d);
                if (lane >= d) w += o;
            }
            warp_tot[cb][lane] = w;
        }
        __syncthreads();                       // sync2

        const float warp_off = (warp > 0) ? warp_tot[cb][warp - 1] : 0.0f;
        const float excl = base + warp_off + (v - run);
        const float total = warp_tot[cb][NW - 1];

        // ---- write out (STG.128) ----
        if (s + 3 < lim) {
            float4 ov;
            ov.x = excl + p0;
            ov.y = excl + p1;
            ov.z = excl + p2;
            ov.w = excl + run;
            *reinterpret_cast<float4*>(out + rowbase + c * CELEMS + s) = ov;
        } else {
            const float pv[4] = {p0, p1, p2, run};
            for (int j = 0; j < 4; j++)
                if (s + j < lim) out[rowbase + c * CELEMS + s + j] = excl + pv[j];
        }

        base += total;
    }
}

extern "C" void kernel_launch(void* const* d_in, const int* in_sizes, int n_in,
                              void* d_out, int out_size)
{
    const float4* X  = (const float4*)d_in[0];   // (B, T, 4) fp32
    const float* SC  = (const float*)d_in[1];    // (B, 4)
    const float* W1i = (const float*)d_in[2];
    const float* b1i = (const float*)d_in[3];
    const float* W2i = (const float*)d_in[4];
    const float* b2i = (const float*)d_in[5];
    const float* W1e = (const float*)d_in[6];
    const float* b1e = (const float*)d_in[7];
    const float* W2e = (const float*)d_in[8];
    const float* b2e = (const float*)d_in[9];
    float* out = (float*)d_out;

    const int B = in_sizes[1] / 4;               // SC is (B,4)
    const int T = in_sizes[0] / (B * 4);         // X is (B,T,4)

    constexpr int NTH = 1024, CEL = 4096, MAXC = 2;
    const int smem_bytes = MAXC * CEL * 16;      // 128 KB
    static bool attr_set = false;
    if (!attr_set) {
        cudaFuncSetAttribute(soc_kernel<NTH, CEL, MAXC>,
                             cudaFuncAttributeMaxDynamicSharedMemorySize, smem_bytes);
        attr_set = true;
    }
    soc_kernel<NTH, CEL, MAXC><<<B, NTH, smem_bytes>>>(
        X, SC, W1i, b1i, W2i, b2i, W1e, b1e, W2e, b2e, out, T);
}

// round 8
// speedup vs baseline: 1.2000x; 1.2000x over previous
#include <cuda_runtime.h>
#include <cuda_bf16.h>
#include <cstdint>

// fast softplus: max(x,0) + log(1 + exp(-|x|)); abs error ~1e-7, tolerance is 1e-3
__device__ __forceinline__ float softplus_f(float x) {
    return fmaxf(x, 0.0f) + __logf(1.0f + __expf(-fabsf(x)));
}

__device__ __forceinline__ uint32_t smem_u32(const void* p) {
    return (uint32_t)__cvta_generic_to_shared(p);
}

#define MBAR_INIT(addr, cnt) \
    asm volatile("mbarrier.init.shared.b64 [%0], %1;" :: "r"(addr), "r"(cnt) : "memory")
#define MBAR_EXPECT_TX(addr, bytes) \
    asm volatile("mbarrier.arrive.expect_tx.shared.b64 _, [%0], %1;" :: "r"(addr), "r"(bytes) : "memory")
#define BULK_G2S(dst_smem, src_gmem, nbytes, bar) \
    asm volatile("cp.async.bulk.shared::cta.global.mbarrier::complete_tx::bytes [%0], [%1], %2, [%3];" \
                 :: "r"(dst_smem), "l"(src_gmem), "r"(nbytes), "r"(bar) : "memory")

__device__ __forceinline__ void mbar_wait_parity(uint32_t bar, uint32_t parity) {
    uint32_t done;
    asm volatile(
        "{\n\t.reg .pred p;\n\t"
        "mbarrier.try_wait.parity.acquire.cta.shared::cta.b64 p, [%1], %2;\n\t"
        "selp.b32 %0, 1, 0, p;\n\t}"
        : "=r"(done) : "r"(bar), "r"(parity) : "memory");
    while (!done) {
        asm volatile(
            "{\n\t.reg .pred p;\n\t"
            "mbarrier.try_wait.parity.acquire.cta.shared::cta.b64 p, [%1], %2, 0x989680;\n\t"
            "selp.b32 %0, 1, 0, p;\n\t}"
            : "=r"(done) : "r"(bar), "r"(parity) : "memory");
    }
}

// One CTA per batch row. Row streamed through a RING of CELEMS-float4 SMEM
// buffers via cp.async.bulk (chunk c+RING issued as soon as chunk c's buffer
// is released). 64KB smem -> 3 CTAs/SM (48 warps): other CTAs compute while
// one waits, hiding TMA fill at wave starts. 4 elems/thread per chunk,
// two-level block scan, cross-chunk (ts,f) + cumsum carry.
template <int NTHREADS, int CELEMS, int RING>
__global__ __launch_bounds__(NTHREADS, 3)
void soc_kernel(const float4* __restrict__ X,       // (B, T, 4)
                const float*  __restrict__ SC,      // (B, 4)
                const float*  __restrict__ W1i, const float* __restrict__ b1i,
                const float*  __restrict__ W2i, const float* __restrict__ b2i,
                const float*  __restrict__ W1e, const float* __restrict__ b1e,
                const float*  __restrict__ W2e, const float* __restrict__ b2e,
                float* __restrict__ out,            // (B, T)
                int T)
{
    extern __shared__ __align__(128) float4 xbuf[];    // RING * CELEMS float4
    __shared__ __align__(8) uint64_t mbar[RING];
    __shared__ float warp_tot[2][32];                  // double-buffered (pad to 32)
    __shared__ float bnd_ts, bnd_f;                    // chunk-boundary carry

    const int b    = blockIdx.x;
    const int tid  = threadIdx.x;
    const int lane = tid & 31;
    const int warp = tid >> 5;
    constexpr int NW = NTHREADS / 32;
    const unsigned FULL = 0xFFFFFFFFu;
    const long long rowbase = (long long)b * (long long)T;
    const int nchunks = (T + CELEMS - 1) / CELEMS;

    if (tid == 0) {
        #pragma unroll
        for (int r = 0; r < RING; r++)
            MBAR_INIT(smem_u32(&mbar[r]), 1);
    }
    __syncthreads();

    // prime the ring
    if (tid == 0) {
        const int prime = (nchunks < RING) ? nchunks : RING;
        for (int c = 0; c < prime; c++) {
            const int lim = min(CELEMS, T - c * CELEMS);
            const uint32_t nbytes = (uint32_t)lim * 16u;
            const uint32_t bar = smem_u32(&mbar[c]);
            MBAR_EXPECT_TX(bar, nbytes);
            BULK_G2S(smem_u32(&xbuf[c * CELEMS]),
                     (const void*)(X + rowbase + (long long)c * CELEMS),
                     nbytes, bar);
        }
    }

    // Per-batch scalars (overlaps with TMA flight)
    const float Q    = SC[b * 4 + 0];
    const float eta0 = SC[b * 4 + 1];
    const float R    = SC[b * 4 + 2];
    const float S3   = SC[b * 4 + 3];
    const float w1e0 = W1e[0], w1e1 = W1e[1];
    const float be1  = b1e[0];
    const float w2e  = W2e[0];
    const float be2  = b2e[0];
    const float w1i0 = W1i[0], w1i1 = W1i[1], w1i2 = W1i[2], w1i3 = W1i[3];
    const float bi1  = b1i[0], w2i = W2i[0], bi2 = b2i[0];
    const float scale = eta0 / (3600.0f * Q);

    float base = 0.0f;   // SOC_init + running cumsum carry (set at c==0)

    for (int c = 0; c < nchunks; c++) {
        const int slot   = c % RING;
        const uint32_t parity = (uint32_t)((c / RING) & 1);
        mbar_wait_parity(smem_u32(&mbar[slot]), parity);

        const float4* xb = &xbuf[slot * CELEMS];
        const int lim = min(CELEMS, T - c * CELEMS);
        const int s = tid * 4;                 // element index within chunk

        if (c == 0) {
            float4 x0 = xb[0];
            float h0 = softplus_f(x0.y * w1i0 + x0.z * w1i1 + x0.w * w1i2 + R * w1i3 + bi1);
            base = S3 * (1.0f + (h0 * w2i + bi2));
        }

        float i0 = 0.f, i1 = 0.f, i2 = 0.f, i3 = 0.f;
        float ts3 = 0.f, f3 = 0.f;             // last-elem (ts,f) for shfl / bnd

        if (s + 3 < lim) {
            float4 v0 = xb[s + 0];
            float4 v1 = xb[s + 1];
            float4 v2 = xb[s + 2];
            float4 v3 = xb[s + 3];
            float h0e = softplus_f(fmaf(v0.y, w1e0, fmaf(v0.z, w1e1, be1)));
            float h1e = softplus_f(fmaf(v1.y, w1e0, fmaf(v1.z, w1e1, be1)));
            float h2e = softplus_f(fmaf(v2.y, w1e0, fmaf(v2.z, w1e1, be1)));
            float h3e = softplus_f(fmaf(v3.y, w1e0, fmaf(v3.z, w1e1, be1)));
            float f0 = scale * (1.0f + fmaf(h0e, w2e, be2)) * v0.y;
            float f1 = scale * (1.0f + fmaf(h1e, w2e, be2)) * v1.y;
            float f2 = scale * (1.0f + fmaf(h2e, w2e, be2)) * v2.y;
            f3       = scale * (1.0f + fmaf(h3e, w2e, be2)) * v3.y;
            ts3 = v3.x;

            float pts = __shfl_up_sync(FULL, ts3, 1);
            float pf  = __shfl_up_sync(FULL, f3, 1);
            if (lane == 0) {
                if (s > 0) {                   // cross-warp boundary: recompute
                    float4 vp = xb[s - 1];
                    float hp = softplus_f(fmaf(vp.y, w1e0, fmaf(vp.z, w1e1, be1)));
                    pts = vp.x;
                    pf  = scale * (1.0f + fmaf(hp, w2e, be2)) * vp.y;
                } else if (c > 0) {            // chunk boundary carry
                    pts = bnd_ts; pf = bnd_f;
                }
            }
            if (c > 0 || s > 0 || lane > 0)    // global t==0 has no increment
                i0 = (v0.x - pts) * pf;
            i1 = (v1.x - v0.x) * f0;
            i2 = (v2.x - v1.x) * f1;
            i3 = (v3.x - v2.x) * f2;
        } else {
            // tail path (rare)
            float pts = 0.f, pf = 0.f;
            bool havep = false;
            if (s < lim && (s > 0 || c > 0)) {
                if (s > 0) {
                    float4 vp = xb[s - 1];
                    float hp = softplus_f(fmaf(vp.y, w1e0, fmaf(vp.z, w1e1, be1)));
                    pts = vp.x;
                    pf  = scale * (1.0f + fmaf(hp, w2e, be2)) * vp.y;
                } else { pts = bnd_ts; pf = bnd_f; }
                havep = true;
            }
            float acc[4] = {0.f, 0.f, 0.f, 0.f};
            for (int j = 0; j < 4; j++) {
                const int t = s + j;
                if (t < lim) {
                    float4 v = xb[t];
                    if (havep) acc[j] = (v.x - pts) * pf;
                    float h = softplus_f(fmaf(v.y, w1e0, fmaf(v.z, w1e1, be1)));
                    pts = v.x;
                    pf  = scale * (1.0f + fmaf(h, w2e, be2)) * v.y;
                    havep = true;
                    ts3 = pts; f3 = pf;
                }
            }
            i0 = acc[0]; i1 = acc[1]; i2 = acc[2]; i3 = acc[3];
        }

        const float p0 = i0;
        const float p1 = p0 + i1;
        const float p2 = p1 + i2;
        const float run = p2 + i3;

        // ---- two-level block scan of per-thread totals ----
        float v = run;
        #pragma unroll
        for (int d = 1; d < 32; d <<= 1) {
            float o = __shfl_up_sync(FULL, v, d);
            if (lane >= d) v += o;
        }
        const int cb = c & 1;
        if (lane == 31) warp_tot[cb][warp] = v;
        __syncthreads();                       // sync1: all xb reads done

        if (s == ((lim - 1) & ~3)) { bnd_ts = ts3; bnd_f = f3; }
        if (warp == 0) {
            // ALL 32 lanes participate (FULL mask requires full-warp convergence);
            // lanes >= NW contribute 0.
            float w = (lane < NW) ? warp_tot[cb][lane] : 0.0f;
            #pragma unroll
            for (int d = 1; d < 32; d <<= 1) {
                float o = __shfl_up_sync(FULL, w, d);
                if (lane >= d) w += o;
            }
            if (lane < NW) warp_tot[cb][lane] = w;
        }
        __syncthreads();                       // sync2: buffer slot reusable

        // refill the freed slot with chunk c+RING
        if (tid == 0 && c + RING < nchunks) {
            const int cn = c + RING;
            const int nlim = min(CELEMS, T - cn * CELEMS);
            const uint32_t nbytes = (uint32_t)nlim * 16u;
            const uint32_t bar = smem_u32(&mbar[slot]);
            MBAR_EXPECT_TX(bar, nbytes);
            BULK_G2S(smem_u32(&xbuf[slot * CELEMS]),
                     (const void*)(X + rowbase + (long long)cn * CELEMS),
                     nbytes, bar);
        }

        const float warp_off = (warp > 0) ? warp_tot[cb][warp - 1] : 0.0f;
        const float excl = base + warp_off + (v - run);
        const float total = warp_tot[cb][NW - 1];

        // ---- write out (STG.128) ----
        if (s + 3 < lim) {
            float4 ov;
            ov.x = excl + p0;
            ov.y = excl + p1;
            ov.z = excl + p2;
            ov.w = excl + run;
            *reinterpret_cast<float4*>(out + rowbase + c * CELEMS + s) = ov;
        } else {
            const float pv[4] = {p0, p1, p2, run};
            for (int j = 0; j < 4; j++)
                if (s + j < lim) out[rowbase + c * CELEMS + s + j] = excl + pv[j];
        }

        base += total;
    }
}

extern "C" void kernel_launch(void* const* d_in, const int* in_sizes, int n_in,
                              void* d_out, int out_size)
{
    const float4* X  = (const float4*)d_in[0];   // (B, T, 4) fp32
    const float* SC  = (const float*)d_in[1];    // (B, 4)
    const float* W1i = (const float*)d_in[2];
    const float* b1i = (const float*)d_in[3];
    const float* W2i = (const float*)d_in[4];
    const float* b2i = (const float*)d_in[5];
    const float* W1e = (const float*)d_in[6];
    const float* b1e = (const float*)d_in[7];
    const float* W2e = (const float*)d_in[8];
    const float* b2e = (const float*)d_in[9];
    float* out = (float*)d_out;

    const int B = in_sizes[1] / 4;               // SC is (B,4)
    const int T = in_sizes[0] / (B * 4);         // X is (B,T,4)

    constexpr int NTH = 512, CEL = 2048, RING = 2;
    const int smem_bytes = RING * CEL * 16;      // 64 KB
    static bool attr_set = false;
    if (!attr_set) {
        cudaFuncSetAttribute(soc_kernel<NTH, CEL, RING>,
                             cudaFuncAttributeMaxDynamicSharedMemorySize, smem_bytes);
        attr_set = true;
    }
    soc_kernel<NTH, CEL, RING><<<B, NTH, smem_bytes>>>(
        X, SC, W1i, b1i, W2i, b2i, W1e, b1e, W2e, b2e, out, T);
}